// round 8
// baseline (speedup 1.0000x reference)
#include <cuda_runtime.h>
#include <cstdint>

#define SBATCH 2
#define SS     192
#define DIN    1024
#define DD     128
#define NPOS   (SBATCH*SS)            /* 384 */
#define P      129
#define OUTSZ  ((size_t)SBATCH*SS*SS*SS)  /* 14,155,776 */

// Scratch: 7 per-position [128x128] matrices.
//  slot 0..3: M[bz,i,j]  = sum_k p[bz,k] * W[i,k,j]   (span_ph, span_pt, ph_sib, pt_sib)
//  slot 4   : A[bx,k,j]  = sum_i p[bx,i] * W_ph_cop[i,k,j]
//  slot 5   : A[bx,k,j]  = sum_i p[bx,i] * W_pt_cop[i,k,j]
//  slot 6   : A'[bx,k,i] = sum_j p[bx,j] * W_pt_cop[i,k,j]
static __device__ float g_scratch[(size_t)7*NPOS*DD*DD];   // 176 MB
static __device__ float g_p [NPOS*DD];
static __device__ float g_sh[NPOS*DD];
static __device__ float g_st[NPOS*DD];

// ---------------------------------------------------------------------------
// Kernel A: three MLPs  (Linear + LeakyReLU(0.1)).  grid(24,3), block 128.
// ---------------------------------------------------------------------------
extern "C" __global__ void __launch_bounds__(128, 1)
k_mlp(const float* __restrict__ x,
      const float* __restrict__ Wp, const float* __restrict__ bp,
      const float* __restrict__ Wh, const float* __restrict__ bh,
      const float* __restrict__ Wt, const float* __restrict__ bt)
{
    extern __shared__ float sx[];                 // 16 x 1024
    const int mt = blockIdx.x, wv = blockIdx.y, tid = threadIdx.x;
    const float* W  = (wv == 0) ? Wp : (wv == 1) ? Wh : Wt;
    const float* bb = (wv == 0) ? bp : (wv == 1) ? bh : bt;
    float* ob       = (wv == 0) ? g_p : (wv == 1) ? g_sh : g_st;

    const float* xr = x + (size_t)mt * 16 * DIN;
    for (int i = tid; i < 16 * DIN; i += 128) sx[i] = xr[i];
    __syncthreads();

    float acc[16];
    const float bias = bb[tid];
#pragma unroll
    for (int m = 0; m < 16; m++) acc[m] = bias;
#pragma unroll 4
    for (int k = 0; k < DIN; k++) {
        const float w = W[k * DD + tid];
#pragma unroll
        for (int m = 0; m < 16; m++) acc[m] = fmaf(sx[m * DIN + k], w, acc[m]);
    }
#pragma unroll
    for (int m = 0; m < 16; m++) {
        float v = acc[m];
        ob[(mt * 16 + m) * DD + tid] = (v > 0.0f) ? v : 0.1f * v;
    }
}

// ---------------------------------------------------------------------------
// Kernel B: stage-1.  out[m,n] = sum_c p[m,c] * B(c,n), 384 x 16384, K=128.
// grid (3, 128, 7), block 256, CTA tile 128x128, 8x8 per thread.
// ---------------------------------------------------------------------------
extern "C" __global__ void __launch_bounds__(256, 1)
k_stage1(const float* __restrict__ W0, const float* __restrict__ W1,
         const float* __restrict__ W2, const float* __restrict__ W3,
         const float* __restrict__ W4, const float* __restrict__ W5)
{
    extern __shared__ float sm[];
    float* sP = sm;                   // 128 x P
    float* sW = sm + 128 * P;         // 128 x P
    const int mt = blockIdx.x, nt = blockIdx.y, var = blockIdx.z;
    const int tid = threadIdx.x;
    const float* W = (var == 0) ? W0 : (var == 1) ? W1 : (var == 2) ? W2 :
                     (var == 3) ? W3 : (var == 4) ? W4 : W5;

    for (int idx = tid; idx < 128 * DD; idx += 256) {
        int r = idx >> 7, c = idx & 127;
        sP[r * P + c] = g_p[(mt * 128 + r) * DD + c];
    }
    if (var <= 3) {            // contract k: B[c,nl] = W[nt, c, nl]   (n=(i=nt, j=nl))
        for (int idx = tid; idx < 128 * DD; idx += 256) {
            int c = idx >> 7, nl = idx & 127;
            sW[c * P + nl] = W[(size_t)nt * 16384 + c * 128 + nl];
        }
    } else if (var <= 5) {     // contract i: B[c,nl] = W[c, nt, nl]   (n=(k=nt, j=nl))
        for (int idx = tid; idx < 128 * DD; idx += 256) {
            int c = idx >> 7, nl = idx & 127;
            sW[c * P + nl] = W[(size_t)c * 16384 + nt * 128 + nl];
        }
    } else {                   // contract j: B[c,nl] = W[nl, nt, c]   (n=(k=nt, i=nl))
        for (int idx = tid; idx < 128 * DD; idx += 256) {
            int nl = idx >> 7, c = idx & 127;
            sW[c * P + nl] = W[(size_t)nl * 16384 + nt * 128 + c];
        }
    }
    __syncthreads();

    const int tx = tid & 15, ty = tid >> 4;
    float acc[8][8];
#pragma unroll
    for (int i = 0; i < 8; i++)
#pragma unroll
        for (int j = 0; j < 8; j++) acc[i][j] = 0.0f;

#pragma unroll 2
    for (int k = 0; k < 128; k++) {
        float a[8], bf[8];
#pragma unroll
        for (int i = 0; i < 8; i++) a[i]  = sP[(ty + 16 * i) * P + k];
#pragma unroll
        for (int j = 0; j < 8; j++) bf[j] = sW[k * P + tx + 16 * j];
#pragma unroll
        for (int i = 0; i < 8; i++)
#pragma unroll
            for (int j = 0; j < 8; j++) acc[i][j] = fmaf(a[i], bf[j], acc[i][j]);
    }

    float* op = g_scratch + ((size_t)var * NPOS + mt * 128) * 16384 + nt * 128;
#pragma unroll
    for (int i = 0; i < 8; i++)
#pragma unroll
        for (int j = 0; j < 8; j++)
            op[(size_t)(ty + 16 * i) * 16384 + tx + 16 * j] = acc[i][j];
}

// ---------------------------------------------------------------------------
// Kernel C: per-(b,s) fused  T = X*B  then  G = T*Y^T  + epilogue.
// grid (384, 7), block 256.  smem rows: sT[0,192) sM[192,320) sU[320,416);
// phase 2 overlays sY on rows [192,384).
//  var 0..3: slot var, out[b,z,x,y], symmetrized (value + mirror writes)
//  var 4   : ph_cop, out[b,x,y,z], full
//  var 5   : pt_cop rows y >= x   (C  = P_b A^T)
//  var 6   : pt_cop rows y <  x   (C' = P_b A'^T)
// ---------------------------------------------------------------------------
extern "C" __global__ void __launch_bounds__(256, 1)
k_stage2(float* __restrict__ out)
{
    extern __shared__ float sm[];
    float* sT = sm;                // 192 x P
    float* sM = sm + 192 * P;      // 128 x P   (phase-1 B operand)
    float* sU = sm + 320 * P;      //  96 x P   (phase-1 A tile)
    float* sY = sm + 192 * P;      // 192 x P   (phase-2, overlays sM+sU)

    const int bz = blockIdx.x, var = blockIdx.y, tid = threadIdx.x;
    const int b = bz / SS, s = bz - b * SS;

    int lo = 0, hi = SS, sym = 0, colB = 0, slot = var;
    const float* Xp; const float* Yp;
    switch (var) {
        case 0: Xp = g_sh; Yp = g_st; sym = 1; break;
        case 1: Xp = g_sh; Yp = g_st; sym = 1; break;
        case 2: Xp = g_sh; Yp = g_sh; sym = 1; break;
        case 3: Xp = g_st; Yp = g_st; sym = 1; break;
        case 4: Xp = g_p;  Yp = g_sh; colB = 1; break;
        case 5: Xp = g_p;  Yp = g_st; colB = 1; lo = s; break;
        default:Xp = g_p;  Yp = g_st; colB = 1; hi = s; slot = 5; break;
    }
    if (var == 6 && s == 0) return;   // block-uniform

    const float* Brow = g_scratch + ((size_t)var * NPOS + bz) * 16384;
    for (int idx = tid; idx < 128 * DD; idx += 256)
        sM[(idx >> 7) * P + (idx & 127)] = Brow[idx];

    const float* Xb = Xp + (size_t)b * SS * DD;
    const int tx = tid & 15, ty = tid >> 4;

    // ---- phase 1: sT[r, c] = sum_k X[r,k] * B(k,c)  (colB: B(k,c)=sM[c,k]) ----
    for (int uh = 0; uh < 2; uh++) {
        for (int idx = tid; idx < 96 * DD; idx += 256) {
            int r = idx >> 7, c = idx & 127;
            sU[r * P + c] = Xb[(uh * 96 + r) * DD + c];
        }
        __syncthreads();
        const int r0 = uh * 96 + ty * 6;
        if (!((r0 + 6 <= lo) || (r0 >= hi))) {
            float acc[6][8];
#pragma unroll
            for (int i = 0; i < 6; i++)
#pragma unroll
                for (int j = 0; j < 8; j++) acc[i][j] = 0.0f;
            if (colB) {
#pragma unroll 2
                for (int k = 0; k < 128; k++) {
                    float a[6], bf[8];
#pragma unroll
                    for (int i = 0; i < 6; i++) a[i]  = sU[(ty * 6 + i) * P + k];
#pragma unroll
                    for (int j = 0; j < 8; j++) bf[j] = sM[(tx + 16 * j) * P + k];
#pragma unroll
                    for (int i = 0; i < 6; i++)
#pragma unroll
                        for (int j = 0; j < 8; j++) acc[i][j] = fmaf(a[i], bf[j], acc[i][j]);
                }
            } else {
#pragma unroll 2
                for (int k = 0; k < 128; k++) {
                    float a[6], bf[8];
#pragma unroll
                    for (int i = 0; i < 6; i++) a[i]  = sU[(ty * 6 + i) * P + k];
#pragma unroll
                    for (int j = 0; j < 8; j++) bf[j] = sM[k * P + tx + 16 * j];
#pragma unroll
                    for (int i = 0; i < 6; i++)
#pragma unroll
                        for (int j = 0; j < 8; j++) acc[i][j] = fmaf(a[i], bf[j], acc[i][j]);
                }
            }
#pragma unroll
            for (int i = 0; i < 6; i++)
#pragma unroll
                for (int j = 0; j < 8; j++)
                    sT[(r0 + i) * P + tx + 16 * j] = acc[i][j];
        }
        __syncthreads();
    }

    // ---- phase 2: G[r,c] = sum_k sT[r,k] * sY[c,k]  + epilogue ----
    const float* Yb = Yp + (size_t)b * SS * DD;
    for (int idx = tid; idx < SS * DD; idx += 256) {
        int r = idx >> 7, c = idx & 127;
        sY[r * P + c] = Yb[r * DD + c];
    }
    __syncthreads();

    const size_t obase = (size_t)slot * OUTSZ + (size_t)(b * SS + s) * SS * SS;
    for (int half = 0; half < 2; half++) {
        const int r0 = ty * 12;
        const int cb = half * 96;
        if ((r0 + 12 <= lo) || (r0 >= hi) || (sym && r0 > cb + 95)) continue;

        float acc[12][6];
#pragma unroll
        for (int i = 0; i < 12; i++)
#pragma unroll
            for (int j = 0; j < 6; j++) acc[i][j] = 0.0f;

#pragma unroll 2
        for (int k = 0; k < 128; k++) {
            float a[12], bf[6];
#pragma unroll
            for (int i = 0; i < 12; i++) a[i]  = sT[(r0 + i) * P + k];
#pragma unroll
            for (int j = 0; j < 6; j++)  bf[j] = sY[(cb + tx + 16 * j) * P + k];
#pragma unroll
            for (int i = 0; i < 12; i++)
#pragma unroll
                for (int j = 0; j < 6; j++) acc[i][j] = fmaf(a[i], bf[j], acc[i][j]);
        }

#pragma unroll
        for (int i = 0; i < 12; i++) {
            const int r = r0 + i;
            if (r < lo || r >= hi) continue;
#pragma unroll
            for (int j = 0; j < 6; j++) {
                const int c = cb + tx + 16 * j;
                const float v = acc[i][j];
                if (sym) {
                    if (r <= c) out[obase + (size_t)r * SS + c] = v;
                    if (r <  c) out[obase + (size_t)c * SS + r] = v;
                } else {
                    out[obase + (size_t)r * SS + c] = v;
                }
            }
        }
    }
}

// ---------------------------------------------------------------------------
extern "C" void kernel_launch(void* const* d_in, const int* in_sizes, int n_in,
                              void* d_out, int out_size)
{
    (void)in_sizes; (void)n_in; (void)out_size;
    const float* x    = (const float*)d_in[0];
    const float* Wp   = (const float*)d_in[1];
    const float* bp   = (const float*)d_in[2];
    const float* Wh   = (const float*)d_in[3];
    const float* bh   = (const float*)d_in[4];
    const float* Wt   = (const float*)d_in[5];
    const float* bt   = (const float*)d_in[6];
    const float* Wsph = (const float*)d_in[7];
    const float* Wspt = (const float*)d_in[8];
    const float* Wphs = (const float*)d_in[9];
    const float* Wpts = (const float*)d_in[10];
    const float* Wphc = (const float*)d_in[11];
    const float* Wptc = (const float*)d_in[12];

    const int smem_mlp = 16 * DIN * 4;          // 64 KB
    const int smem_s1  = 2 * 128 * P * 4;       // 132 KB
    const int smem_s2  = 416 * P * 4;           // 214.7 KB
    cudaFuncSetAttribute(k_mlp,    cudaFuncAttributeMaxDynamicSharedMemorySize, smem_mlp);
    cudaFuncSetAttribute(k_stage1, cudaFuncAttributeMaxDynamicSharedMemorySize, smem_s1);
    cudaFuncSetAttribute(k_stage2, cudaFuncAttributeMaxDynamicSharedMemorySize, smem_s2);

    k_mlp<<<dim3(24, 3), 128, smem_mlp>>>(x, Wp, bp, Wh, bh, Wt, bt);
    k_stage1<<<dim3(3, 128, 7), 256, smem_s1>>>(Wsph, Wspt, Wphs, Wpts, Wphc, Wptc);
    k_stage2<<<dim3(NPOS, 7), 256, smem_s2>>>((float*)d_out);
}

// round 10
// speedup vs baseline: 1.1085x; 1.1085x over previous
#include <cuda_runtime.h>
#include <cstdint>

#define SBATCH 2
#define SS     192
#define DIN    1024
#define DD     128
#define NPOS   (SBATCH*SS)            /* 384 */
#define P      130                    /* even: 8B-aligned k-pairs; stride mod 32 == 2 */
#define OUTSZ  ((size_t)SBATCH*SS*SS*SS)  /* 14,155,776 */

typedef unsigned long long u64;

__device__ __forceinline__ void fma2(u64& d, u64 a, u64 b) {
    asm("fma.rn.f32x2 %0, %1, %2, %0;" : "+l"(d) : "l"(a), "l"(b));
}
__device__ __forceinline__ float hadd2(u64 v) {
    float x, y;
    asm("mov.b64 {%0,%1}, %2;" : "=f"(x), "=f"(y) : "l"(v));
    return x + y;
}

// Scratch: 7 per-position [128x128] matrices.
//  slot 0..3: M[bz,i,j]  = sum_k p[bz,k] * W[i,k,j]   (span_ph, span_pt, ph_sib, pt_sib)
//  slot 4   : A[bx,k,j]  = sum_i p[bx,i] * W_ph_cop[i,k,j]
//  slot 5   : A[bx,k,j]  = sum_i p[bx,i] * W_pt_cop[i,k,j]
//  slot 6   : A'[bx,k,i] = sum_j p[bx,j] * W_pt_cop[i,k,j]
static __device__ float g_scratch[(size_t)7*NPOS*DD*DD];   // 176 MB
static __device__ float g_p [NPOS*DD];
static __device__ float g_sh[NPOS*DD];
static __device__ float g_st[NPOS*DD];

// ---------------------------------------------------------------------------
// Kernel A: three MLPs (Linear + LeakyReLU(0.1)).  grid(48,3), block 128.
// 8 rows per CTA; W staged k-major in smem chunks; k-packed FFMA2 core.
// ---------------------------------------------------------------------------
#define KC 128   /* K chunk */
extern "C" __global__ void __launch_bounds__(128, 1)
k_mlp(const float* __restrict__ x,
      const float* __restrict__ Wp, const float* __restrict__ bp,
      const float* __restrict__ Wh, const float* __restrict__ bh,
      const float* __restrict__ Wt, const float* __restrict__ bt)
{
    extern __shared__ float sm[];
    float* sx  = sm;              // 8 x 1024 (k-contiguous)
    float* sWt = sm + 8 * DIN;    // 128 cols x P (k-contiguous)
    const int mt = blockIdx.x, wv = blockIdx.y, tid = threadIdx.x;
    const float* W  = (wv == 0) ? Wp : (wv == 1) ? Wh : Wt;
    const float* bb = (wv == 0) ? bp : (wv == 1) ? bh : bt;
    float* ob       = (wv == 0) ? g_p : (wv == 1) ? g_sh : g_st;

    const float* xr = x + (size_t)mt * 8 * DIN;
    for (int i = tid; i < 8 * DIN; i += 128) sx[i] = xr[i];

    u64 acc[8];
#pragma unroll
    for (int m = 0; m < 8; m++) acc[m] = 0ull;

    for (int kc = 0; kc < DIN; kc += KC) {
        __syncthreads();
        // stage W[kc..kc+KC) transposed: sWt[col][k]
        for (int idx = tid; idx < KC * DD; idx += 128) {
            int k = idx >> 7, c = idx & 127;
            sWt[c * P + k] = W[(size_t)(kc + k) * DD + c];
        }
        __syncthreads();
#pragma unroll 4
        for (int kp = 0; kp < KC / 2; kp++) {
            const u64 w2 = *(const u64*)&sWt[tid * P + 2 * kp];
#pragma unroll
            for (int m = 0; m < 8; m++) {
                const u64 a2 = *(const u64*)&sx[m * DIN + kc + 2 * kp];
                fma2(acc[m], a2, w2);
            }
        }
    }
    const float bias = bb[tid];
#pragma unroll
    for (int m = 0; m < 8; m++) {
        float v = hadd2(acc[m]) + bias;
        ob[(mt * 8 + m) * DD + tid] = (v > 0.0f) ? v : 0.1f * v;
    }
}

// ---------------------------------------------------------------------------
// Kernel B: stage-1.  out[m,n] = sum_c p[m,c] * B(c,n), 384 x 16384, K=128.
// grid (3, 128, 7), block 256, CTA tile 128x128, 8x8 per thread, k-packed.
// ---------------------------------------------------------------------------
extern "C" __global__ void __launch_bounds__(256, 1)
k_stage1(const float* __restrict__ W0, const float* __restrict__ W1,
         const float* __restrict__ W2, const float* __restrict__ W3,
         const float* __restrict__ W4, const float* __restrict__ W5)
{
    extern __shared__ float sm[];
    float* sP  = sm;                  // 128 rows x P  (k-contiguous)
    float* sWt = sm + 128 * P;        // 128 cols x P  (k-contiguous)
    const int mt = blockIdx.x, nt = blockIdx.y, var = blockIdx.z;
    const int tid = threadIdx.x;
    const float* W = (var == 0) ? W0 : (var == 1) ? W1 : (var == 2) ? W2 :
                     (var == 3) ? W3 : (var == 4) ? W4 : W5;

    for (int idx = tid; idx < 128 * DD; idx += 256) {
        int r = idx >> 7, c = idx & 127;
        sP[r * P + c] = g_p[(mt * 128 + r) * DD + c];
    }
    if (var <= 3) {            // contract k: B[c,nl] = W[nt, c, nl]
        for (int idx = tid; idx < 128 * DD; idx += 256) {
            int c = idx >> 7, nl = idx & 127;
            sWt[nl * P + c] = W[(size_t)nt * 16384 + c * 128 + nl];
        }
    } else if (var <= 5) {     // contract i: B[c,nl] = W[c, nt, nl]
        for (int idx = tid; idx < 128 * DD; idx += 256) {
            int c = idx >> 7, nl = idx & 127;
            sWt[nl * P + c] = W[(size_t)c * 16384 + nt * 128 + nl];
        }
    } else {                   // contract j: B[c,nl] = W[nl, nt, c]
        for (int idx = tid; idx < 128 * DD; idx += 256) {
            int nl = idx >> 7, c = idx & 127;
            sWt[nl * P + c] = W[(size_t)nl * 16384 + nt * 128 + c];
        }
    }
    __syncthreads();

    const int tx = tid & 15, ty = tid >> 4;
    u64 acc[8][8];
#pragma unroll
    for (int i = 0; i < 8; i++)
#pragma unroll
        for (int j = 0; j < 8; j++) acc[i][j] = 0ull;

#pragma unroll 4
    for (int kp = 0; kp < 64; kp++) {
        u64 a2[8], b2[8];
#pragma unroll
        for (int i = 0; i < 8; i++) a2[i] = *(const u64*)&sP [(ty * 8 + i)  * P + 2 * kp];
#pragma unroll
        for (int j = 0; j < 8; j++) b2[j] = *(const u64*)&sWt[(tx + 16 * j) * P + 2 * kp];
#pragma unroll
        for (int i = 0; i < 8; i++)
#pragma unroll
            for (int j = 0; j < 8; j++) fma2(acc[i][j], a2[i], b2[j]);
    }

    float* op = g_scratch + ((size_t)var * NPOS + mt * 128) * 16384 + nt * 128;
#pragma unroll
    for (int i = 0; i < 8; i++)
#pragma unroll
        for (int j = 0; j < 8; j++)
            op[(size_t)(ty * 8 + i) * 16384 + tx + 16 * j] = hadd2(acc[i][j]);
}

// ---------------------------------------------------------------------------
// Kernel C: per-(b,s) fused  T = X*B  then  G = T*Y^T  + epilogue.
// grid (384, 7), block 256.  All smem operands k-contiguous, k-packed FFMA2.
//  var 0..3: slot var, out[b,z,x,y], symmetrized (value + mirror writes)
//  var 4   : ph_cop, out[b,x,y,z], full
//  var 5   : pt_cop rows y >= x
//  var 6   : pt_cop rows y <  x
// ---------------------------------------------------------------------------
extern "C" __global__ void __launch_bounds__(256, 1)
k_stage2(float* __restrict__ out)
{
    extern __shared__ float sm[];
    float* sT  = sm;               // 192 rows x P  (d-contiguous)
    float* sMt = sm + 192 * P;     // 128 cols x P  (k-contiguous)  phase 1
    float* sU  = sm + 320 * P;     //  96 rows x P  (k-contiguous)  phase 1
    float* sY  = sm + 192 * P;     // 192 rows x P  (d-contiguous)  phase 2 overlay

    const int bz = blockIdx.x, var = blockIdx.y, tid = threadIdx.x;
    const int b = bz / SS, s = bz - b * SS;

    int lo = 0, hi = SS, sym = 0, colB = 0, slot = var;
    const float* Xp; const float* Yp;
    switch (var) {
        case 0: Xp = g_sh; Yp = g_st; sym = 1; break;
        case 1: Xp = g_sh; Yp = g_st; sym = 1; break;
        case 2: Xp = g_sh; Yp = g_sh; sym = 1; break;
        case 3: Xp = g_st; Yp = g_st; sym = 1; break;
        case 4: Xp = g_p;  Yp = g_sh; colB = 1; break;
        case 5: Xp = g_p;  Yp = g_st; colB = 1; lo = s; break;
        default:Xp = g_p;  Yp = g_st; colB = 1; hi = s; slot = 5; break;
    }
    if (var == 6 && s == 0) return;   // block-uniform

    // Load B operand into sMt[c][k]:
    //  row-variant (var<=3): B(k,c) = Brow[k*128+c]  -> transpose on store
    //  col-variant (var>=4): B(k,c) = Brow[c*128+k]  -> direct
    const float* Brow = g_scratch + ((size_t)var * NPOS + bz) * 16384;
    if (colB) {
        for (int idx = tid; idx < 128 * DD; idx += 256)
            sMt[(idx >> 7) * P + (idx & 127)] = Brow[idx];
    } else {
        for (int idx = tid; idx < 128 * DD; idx += 256) {
            int k = idx >> 7, c = idx & 127;
            sMt[c * P + k] = Brow[idx];
        }
    }

    const float* Xb = Xp + (size_t)b * SS * DD;
    const int tx = tid & 15, ty = tid >> 4;

    // ---- phase 1: sT[r,c] = sum_k X[r,k] * B(k,c),  6x8 per thread, k-packed ----
    for (int uh = 0; uh < 2; uh++) {
        for (int idx = tid; idx < 96 * DD; idx += 256) {
            int r = idx >> 7, c = idx & 127;
            sU[r * P + c] = Xb[(uh * 96 + r) * DD + c];
        }
        __syncthreads();
        const int r0 = uh * 96 + ty * 6;
        if (!((r0 + 6 <= lo) || (r0 >= hi))) {
            u64 acc[6][8];
#pragma unroll
            for (int i = 0; i < 6; i++)
#pragma unroll
                for (int j = 0; j < 8; j++) acc[i][j] = 0ull;
#pragma unroll 4
            for (int kp = 0; kp < 64; kp++) {
                u64 a2[6], b2[8];
#pragma unroll
                for (int i = 0; i < 6; i++) a2[i] = *(const u64*)&sU [(ty * 6 + i)  * P + 2 * kp];
#pragma unroll
                for (int j = 0; j < 8; j++) b2[j] = *(const u64*)&sMt[(tx + 16 * j) * P + 2 * kp];
#pragma unroll
                for (int i = 0; i < 6; i++)
#pragma unroll
                    for (int j = 0; j < 8; j++) fma2(acc[i][j], a2[i], b2[j]);
            }
#pragma unroll
            for (int i = 0; i < 6; i++)
#pragma unroll
                for (int j = 0; j < 8; j++)
                    sT[(r0 + i) * P + tx + 16 * j] = hadd2(acc[i][j]);
        }
        __syncthreads();
    }

    // ---- phase 2: G[r,c] = sum_d sT[r,d] * sY[c,d], four 96x96 sub-tiles,
    //      6x6 per thread, k-packed ----
    const float* Yb = Yp + (size_t)b * SS * DD;
    for (int idx = tid; idx < SS * DD; idx += 256) {
        int r = idx >> 7, c = idx & 127;
        sY[r * P + c] = Yb[r * DD + c];
    }
    __syncthreads();

    const size_t obase = (size_t)slot * OUTSZ + (size_t)(b * SS + s) * SS * SS;
    for (int rh = 0; rh < 2; rh++) {
        const int r0 = rh * 96 + ty * 6;
        if ((r0 + 6 <= lo) || (r0 >= hi)) continue;
        for (int ch = 0; ch < 2; ch++) {
            if (sym && rh == 1 && ch == 0) continue;               // fully lower
            if (sym && rh == ch && ty * 6 > tx + 85) continue;     // below band

            u64 acc[6][6];
#pragma unroll
            for (int i = 0; i < 6; i++)
#pragma unroll
                for (int j = 0; j < 6; j++) acc[i][j] = 0ull;
#pragma unroll 4
            for (int kp = 0; kp < 64; kp++) {
                u64 a2[6], b2[6];
#pragma unroll
                for (int i = 0; i < 6; i++)
                    a2[i] = *(const u64*)&sT[(r0 + i) * P + 2 * kp];
#pragma unroll
                for (int j = 0; j < 6; j++)
                    b2[j] = *(const u64*)&sY[(ch * 96 + tx + 16 * j) * P + 2 * kp];
#pragma unroll
                for (int i = 0; i < 6; i++)
#pragma unroll
                    for (int j = 0; j < 6; j++) fma2(acc[i][j], a2[i], b2[j]);
            }

#pragma unroll
            for (int i = 0; i < 6; i++) {
                const int r = r0 + i;
                if (r < lo || r >= hi) continue;
#pragma unroll
                for (int j = 0; j < 6; j++) {
                    const int c = ch * 96 + tx + 16 * j;
                    const float v = hadd2(acc[i][j]);
                    if (sym) {
                        if (r <= c) out[obase + (size_t)r * SS + c] = v;
                        if (r <  c) out[obase + (size_t)c * SS + r] = v;
                    } else {
                        out[obase + (size_t)r * SS + c] = v;
                    }
                }
            }
        }
    }
}

// ---------------------------------------------------------------------------
extern "C" void kernel_launch(void* const* d_in, const int* in_sizes, int n_in,
                              void* d_out, int out_size)
{
    (void)in_sizes; (void)n_in; (void)out_size;
    const float* x    = (const float*)d_in[0];
    const float* Wp   = (const float*)d_in[1];
    const float* bp   = (const float*)d_in[2];
    const float* Wh   = (const float*)d_in[3];
    const float* bh   = (const float*)d_in[4];
    const float* Wt   = (const float*)d_in[5];
    const float* bt   = (const float*)d_in[6];
    const float* Wsph = (const float*)d_in[7];
    const float* Wspt = (const float*)d_in[8];
    const float* Wphs = (const float*)d_in[9];
    const float* Wpts = (const float*)d_in[10];
    const float* Wphc = (const float*)d_in[11];
    const float* Wptc = (const float*)d_in[12];

    const int smem_mlp = (8 * DIN + 128 * P) * 4;   // 99.3 KB
    const int smem_s1  = 2 * 128 * P * 4;           // 133.1 KB
    const int smem_s2  = 416 * P * 4;               // 216.3 KB
    cudaFuncSetAttribute(k_mlp,    cudaFuncAttributeMaxDynamicSharedMemorySize, smem_mlp);
    cudaFuncSetAttribute(k_stage1, cudaFuncAttributeMaxDynamicSharedMemorySize, smem_s1);
    cudaFuncSetAttribute(k_stage2, cudaFuncAttributeMaxDynamicSharedMemorySize, smem_s2);

    k_mlp<<<dim3(48, 3), 128, smem_mlp>>>(x, Wp, bp, Wh, bh, Wt, bt);
    k_stage1<<<dim3(3, 128, 7), 256, smem_s1>>>(Wsph, Wspt, Wphs, Wpts, Wphc, Wptc);
    k_stage2<<<dim3(NPOS, 7), 256, smem_s2>>>((float*)d_out);
}

// round 12
// speedup vs baseline: 1.1500x; 1.0375x over previous
#include <cuda_runtime.h>
#include <cstdint>

#define SBATCH 2
#define SS     192
#define DIN    1024
#define DD     128
#define NPOS   (SBATCH*SS)            /* 384 */
#define P      130                    /* even: 8B-aligned k-pairs; stride mod 32 == 2 */
#define OUTSZ  ((size_t)SBATCH*SS*SS*SS)  /* 14,155,776 */

typedef unsigned long long u64;

__device__ __forceinline__ void fma2(u64& d, u64 a, u64 b) {
    asm("fma.rn.f32x2 %0, %1, %2, %0;" : "+l"(d) : "l"(a), "l"(b));
}
__device__ __forceinline__ float hadd2(u64 v) {
    float x, y;
    asm("mov.b64 {%0,%1}, %2;" : "=f"(x), "=f"(y) : "l"(v));
    return x + y;
}

// Scratch: 7 per-position [128x128] matrices.
//  slot 0..3: M[bz,i,j]  = sum_k p[bz,k] * W[i,k,j]   (span_ph, span_pt, ph_sib, pt_sib)
//  slot 4   : A[bx,k,j]  = sum_i p[bx,i] * W_ph_cop[i,k,j]
//  slot 5   : A[bx,k,j]  = sum_i p[bx,i] * W_pt_cop[i,k,j]
//  slot 6   : A'[bx,k,i] = sum_j p[bx,j] * W_pt_cop[i,k,j]
static __device__ float g_scratch[(size_t)7*NPOS*DD*DD];   // 176 MB
static __device__ float g_p [NPOS*DD];
static __device__ float g_sh[NPOS*DD];
static __device__ float g_st[NPOS*DD];

// ---------------------------------------------------------------------------
// Kernel A: three MLPs (Linear + LeakyReLU(0.1)).  grid(48,3), block 128.
// 8 rows per CTA; W staged k-major in smem chunks; k-packed FFMA2 core.
// ---------------------------------------------------------------------------
#define KC 128   /* K chunk */
extern "C" __global__ void __launch_bounds__(128, 1)
k_mlp(const float* __restrict__ x,
      const float* __restrict__ Wp, const float* __restrict__ bp,
      const float* __restrict__ Wh, const float* __restrict__ bh,
      const float* __restrict__ Wt, const float* __restrict__ bt)
{
    extern __shared__ float sm[];
    float* sx  = sm;              // 8 x 1024 (k-contiguous)
    float* sWt = sm + 8 * DIN;    // 128 cols x P (k-contiguous)
    const int mt = blockIdx.x, wv = blockIdx.y, tid = threadIdx.x;
    const float* W  = (wv == 0) ? Wp : (wv == 1) ? Wh : Wt;
    const float* bb = (wv == 0) ? bp : (wv == 1) ? bh : bt;
    float* ob       = (wv == 0) ? g_p : (wv == 1) ? g_sh : g_st;

    const float* xr = x + (size_t)mt * 8 * DIN;
    for (int i = tid; i < 8 * DIN; i += 128) sx[i] = xr[i];

    u64 acc[8];
#pragma unroll
    for (int m = 0; m < 8; m++) acc[m] = 0ull;

    for (int kc = 0; kc < DIN; kc += KC) {
        __syncthreads();
        // stage W[kc..kc+KC) transposed: sWt[col][k]
        for (int idx = tid; idx < KC * DD; idx += 128) {
            int k = idx >> 7, c = idx & 127;
            sWt[c * P + k] = W[(size_t)(kc + k) * DD + c];
        }
        __syncthreads();
#pragma unroll 4
        for (int kp = 0; kp < KC / 2; kp++) {
            const u64 w2 = *(const u64*)&sWt[tid * P + 2 * kp];
#pragma unroll
            for (int m = 0; m < 8; m++) {
                const u64 a2 = *(const u64*)&sx[m * DIN + kc + 2 * kp];
                fma2(acc[m], a2, w2);
            }
        }
    }
    const float bias = bb[tid];
#pragma unroll
    for (int m = 0; m < 8; m++) {
        float v = hadd2(acc[m]) + bias;
        ob[(mt * 8 + m) * DD + tid] = (v > 0.0f) ? v : 0.1f * v;
    }
}

// ---------------------------------------------------------------------------
// Kernel B: stage-1.  out[m,n] = sum_c p[m,c] * B(c,n), 384 x 16384, K=128.
// grid (3, 128, 7), block 256, CTA tile 128x128, 8x8 per thread, k-packed.
// ---------------------------------------------------------------------------
extern "C" __global__ void __launch_bounds__(256, 1)
k_stage1(const float* __restrict__ W0, const float* __restrict__ W1,
         const float* __restrict__ W2, const float* __restrict__ W3,
         const float* __restrict__ W4, const float* __restrict__ W5)
{
    extern __shared__ float sm[];
    float* sP  = sm;                  // 128 rows x P  (k-contiguous)
    float* sWt = sm + 128 * P;        // 128 cols x P  (k-contiguous)
    const int mt = blockIdx.x, nt = blockIdx.y, var = blockIdx.z;
    const int tid = threadIdx.x;
    const float* W = (var == 0) ? W0 : (var == 1) ? W1 : (var == 2) ? W2 :
                     (var == 3) ? W3 : (var == 4) ? W4 : W5;

    for (int idx = tid; idx < 128 * DD; idx += 256) {
        int r = idx >> 7, c = idx & 127;
        sP[r * P + c] = g_p[(mt * 128 + r) * DD + c];
    }
    if (var <= 3) {            // contract k: B[c,nl] = W[nt, c, nl]
        for (int idx = tid; idx < 128 * DD; idx += 256) {
            int c = idx >> 7, nl = idx & 127;
            sWt[nl * P + c] = W[(size_t)nt * 16384 + c * 128 + nl];
        }
    } else if (var <= 5) {     // contract i: B[c,nl] = W[c, nt, nl]
        for (int idx = tid; idx < 128 * DD; idx += 256) {
            int c = idx >> 7, nl = idx & 127;
            sWt[nl * P + c] = W[(size_t)c * 16384 + nt * 128 + nl];
        }
    } else {                   // contract j: B[c,nl] = W[nl, nt, c]
        for (int idx = tid; idx < 128 * DD; idx += 256) {
            int nl = idx >> 7, c = idx & 127;
            sWt[nl * P + c] = W[(size_t)nl * 16384 + nt * 128 + c];
        }
    }
    __syncthreads();

    const int tx = tid & 15, ty = tid >> 4;
    u64 acc[8][8];
#pragma unroll
    for (int i = 0; i < 8; i++)
#pragma unroll
        for (int j = 0; j < 8; j++) acc[i][j] = 0ull;

#pragma unroll 4
    for (int kp = 0; kp < 64; kp++) {
        u64 a2[8], b2[8];
#pragma unroll
        for (int i = 0; i < 8; i++) a2[i] = *(const u64*)&sP [(ty * 8 + i)  * P + 2 * kp];
#pragma unroll
        for (int j = 0; j < 8; j++) b2[j] = *(const u64*)&sWt[(tx + 16 * j) * P + 2 * kp];
#pragma unroll
        for (int i = 0; i < 8; i++)
#pragma unroll
            for (int j = 0; j < 8; j++) fma2(acc[i][j], a2[i], b2[j]);
    }

    float* op = g_scratch + ((size_t)var * NPOS + mt * 128) * 16384 + nt * 128;
#pragma unroll
    for (int i = 0; i < 8; i++)
#pragma unroll
        for (int j = 0; j < 8; j++)
            op[(size_t)(ty * 8 + i) * 16384 + tx + 16 * j] = hadd2(acc[i][j]);
}

// ---------------------------------------------------------------------------
// Kernel C: per-(b,s) fused  T = X*B  then  G = T*Y^T  + epilogue.
// grid (384, 7), block 256.  All smem operands k-contiguous, k-packed FFMA2.
//  var 0..3: slot var, out[b,z,x,y], symmetrized (value + mirror writes)
//  var 4   : ph_cop, out[b,x,y,z], full
//  var 5   : pt_cop rows y >= x
//  var 6   : pt_cop rows y <  x
// ---------------------------------------------------------------------------
extern "C" __global__ void __launch_bounds__(256, 1)
k_stage2(float* __restrict__ out)
{
    extern __shared__ float sm[];
    float* sT  = sm;               // 192 rows x P  (d-contiguous)
    float* sMt = sm + 192 * P;     // 128 cols x P  (k-contiguous)  phase 1
    float* sU  = sm + 320 * P;     //  96 rows x P  (k-contiguous)  phase 1
    float* sY  = sm + 192 * P;     // 192 rows x P  (d-contiguous)  phase 2 overlay

    const int bz = blockIdx.x, var = blockIdx.y, tid = threadIdx.x;
    const int b = bz / SS, s = bz - b * SS;

    int lo = 0, hi = SS, sym = 0, colB = 0, slot = var;
    const float* Xp; const float* Yp;
    switch (var) {
        case 0: Xp = g_sh; Yp = g_st; sym = 1; break;
        case 1: Xp = g_sh; Yp = g_st; sym = 1; break;
        case 2: Xp = g_sh; Yp = g_sh; sym = 1; break;
        case 3: Xp = g_st; Yp = g_st; sym = 1; break;
        case 4: Xp = g_p;  Yp = g_sh; colB = 1; break;
        case 5: Xp = g_p;  Yp = g_st; colB = 1; lo = s; break;
        default:Xp = g_p;  Yp = g_st; colB = 1; hi = s; slot = 5; break;
    }
    if (var == 6 && s == 0) return;   // block-uniform

    // Load B operand into sMt[c][k]:
    //  row-variant (var<=3): B(k,c) = Brow[k*128+c]  -> transpose on store
    //  col-variant (var>=4): B(k,c) = Brow[c*128+k]  -> direct
    const float* Brow = g_scratch + ((size_t)var * NPOS + bz) * 16384;
    if (colB) {
        for (int idx = tid; idx < 128 * DD; idx += 256)
            sMt[(idx >> 7) * P + (idx & 127)] = Brow[idx];
    } else {
        for (int idx = tid; idx < 128 * DD; idx += 256) {
            int k = idx >> 7, c = idx & 127;
            sMt[c * P + k] = Brow[idx];
        }
    }

    const float* Xb = Xp + (size_t)b * SS * DD;
    const int tx = tid & 15, ty = tid >> 4;

    // ---- phase 1: sT[r,c] = sum_k X[r,k] * B(k,c),  6x8 per thread, k-packed ----
    for (int uh = 0; uh < 2; uh++) {
        for (int idx = tid; idx < 96 * DD; idx += 256) {
            int r = idx >> 7, c = idx & 127;
            sU[r * P + c] = Xb[(uh * 96 + r) * DD + c];
        }
        __syncthreads();
        const int r0 = uh * 96 + ty * 6;
        if (!((r0 + 6 <= lo) || (r0 >= hi))) {
            u64 acc[6][8];
#pragma unroll
            for (int i = 0; i < 6; i++)
#pragma unroll
                for (int j = 0; j < 8; j++) acc[i][j] = 0ull;
#pragma unroll 4
            for (int kp = 0; kp < 64; kp++) {
                u64 a2[6], b2[8];
#pragma unroll
                for (int i = 0; i < 6; i++) a2[i] = *(const u64*)&sU [(ty * 6 + i)  * P + 2 * kp];
#pragma unroll
                for (int j = 0; j < 8; j++) b2[j] = *(const u64*)&sMt[(tx + 16 * j) * P + 2 * kp];
#pragma unroll
                for (int i = 0; i < 6; i++)
#pragma unroll
                    for (int j = 0; j < 8; j++) fma2(acc[i][j], a2[i], b2[j]);
            }
#pragma unroll
            for (int i = 0; i < 6; i++)
#pragma unroll
                for (int j = 0; j < 8; j++)
                    sT[(r0 + i) * P + tx + 16 * j] = hadd2(acc[i][j]);
        }
        __syncthreads();
    }

    // ---- phase 2: G[r,c] = sum_d sT[r,d] * sY[c,d], four 96x96 sub-tiles,
    //      6x6 per thread, k-packed ----
    const float* Yb = Yp + (size_t)b * SS * DD;
    for (int idx = tid; idx < SS * DD; idx += 256) {
        int r = idx >> 7, c = idx & 127;
        sY[r * P + c] = Yb[r * DD + c];
    }
    __syncthreads();

    const size_t obase = (size_t)slot * OUTSZ + (size_t)(b * SS + s) * SS * SS;
    for (int rh = 0; rh < 2; rh++) {
        const int r0 = rh * 96 + ty * 6;
        if ((r0 + 6 <= lo) || (r0 >= hi)) continue;
        for (int ch = 0; ch < 2; ch++) {
            if (sym && rh == 1 && ch == 0) continue;               // fully lower
            if (sym && rh == ch && ty * 6 > tx + 85) continue;     // below band

            u64 acc[6][6];
#pragma unroll
            for (int i = 0; i < 6; i++)
#pragma unroll
                for (int j = 0; j < 6; j++) acc[i][j] = 0ull;
#pragma unroll 4
            for (int kp = 0; kp < 64; kp++) {
                u64 a2[6], b2[6];
#pragma unroll
                for (int i = 0; i < 6; i++)
                    a2[i] = *(const u64*)&sT[(r0 + i) * P + 2 * kp];
#pragma unroll
                for (int j = 0; j < 6; j++)
                    b2[j] = *(const u64*)&sY[(ch * 96 + tx + 16 * j) * P + 2 * kp];
#pragma unroll
                for (int i = 0; i < 6; i++)
#pragma unroll
                    for (int j = 0; j < 6; j++) fma2(acc[i][j], a2[i], b2[j]);
            }

#pragma unroll
            for (int i = 0; i < 6; i++) {
                const int r = r0 + i;
                if (r < lo || r >= hi) continue;
#pragma unroll
                for (int j = 0; j < 6; j++) {
                    const int c = ch * 96 + tx + 16 * j;
                    const float v = hadd2(acc[i][j]);
                    if (sym) {
                        if (r <= c) out[obase + (size_t)r * SS + c] = v;
                        if (r <  c) out[obase + (size_t)c * SS + r] = v;
                    } else {
                        out[obase + (size_t)r * SS + c] = v;
                    }
                }
            }
        }
    }
}

// ---------------------------------------------------------------------------
extern "C" void kernel_launch(void* const* d_in, const int* in_sizes, int n_in,
                              void* d_out, int out_size)
{
    (void)in_sizes; (void)n_in; (void)out_size;
    const float* x    = (const float*)d_in[0];
    const float* Wp   = (const float*)d_in[1];
    const float* bp   = (const float*)d_in[2];
    const float* Wh   = (const float*)d_in[3];
    const float* bh   = (const float*)d_in[4];
    const float* Wt   = (const float*)d_in[5];
    const float* bt   = (const float*)d_in[6];
    const float* Wsph = (const float*)d_in[7];
    const float* Wspt = (const float*)d_in[8];
    const float* Wphs = (const float*)d_in[9];
    const float* Wpts = (const float*)d_in[10];
    const float* Wphc = (const float*)d_in[11];
    const float* Wptc = (const float*)d_in[12];

    const int smem_mlp = (8 * DIN + 128 * P) * 4;   // 99.3 KB
    const int smem_s1  = 2 * 128 * P * 4;           // 133.1 KB
    const int smem_s2  = 416 * P * 4;               // 216.3 KB
    cudaFuncSetAttribute(k_mlp,    cudaFuncAttributeMaxDynamicSharedMemorySize, smem_mlp);
    cudaFuncSetAttribute(k_stage1, cudaFuncAttributeMaxDynamicSharedMemorySize, smem_s1);
    cudaFuncSetAttribute(k_stage2, cudaFuncAttributeMaxDynamicSharedMemorySize, smem_s2);

    k_mlp<<<dim3(48, 3), 128, smem_mlp>>>(x, Wp, bp, Wh, bh, Wt, bt);
    k_stage1<<<dim3(3, 128, 7), 256, smem_s1>>>(Wsph, Wspt, Wphs, Wpts, Wphc, Wptc);
    k_stage2<<<dim3(NPOS, 7), 256, smem_s2>>>((float*)d_out);
}